// round 2
// baseline (speedup 1.0000x reference)
#include <cuda_runtime.h>
#include <math.h>

#define HID 1024
#define KD  1024
#define NLEAF 8192
#define DEPTH 13

// ---------------- device scratch (static globals: no allocation in kernel_launch) ----
__device__ float g_h[2][NLEAF * HID];          // ping-pong h per level
__device__ float g_c[2][NLEAF * HID];          // ping-pong c per level
__device__ float g_xw[(size_t)NLEAF * 4 * HID];// leaf x@Wcat^T
__device__ float g_g3[(NLEAF / 2) * 3 * HID];  // per-level hs @ [Ui;Uo;Uu]^T
__device__ float g_gf[NLEAF * HID];            // per-level h_child @ Uf^T
__device__ float g_wcat[4 * HID * KD];         // [Wi;Wo;Wu;Wf] rows
__device__ float g_ucat3[3 * HID * KD];        // [Ui;Uo;Uu] rows
__device__ float g_opg[4 * 4 * HID];           // op gate table (bias folded)
__device__ float g_lc3[3 * HID];               // leaf (h0+h1)@U_{i,o,u}^T + b
__device__ float g_lf[2 * HID];                // leaf h_init[k]@Uf^T + b_f

__device__ __forceinline__ float sigf(float x) { return 1.0f / (1.0f + expf(-x)); }

// ---------------- precompute: OPG table + leaf constants -----------------------------
__global__ void precompute_kernel(
    const float* __restrict__ W_i, const float* __restrict__ W_o,
    const float* __restrict__ W_u, const float* __restrict__ W_f,
    const float* __restrict__ U_i, const float* __restrict__ U_o,
    const float* __restrict__ U_u, const float* __restrict__ U_f,
    const float* __restrict__ b_i, const float* __restrict__ b_o,
    const float* __restrict__ b_u, const float* __restrict__ b_f,
    const float* __restrict__ op_emb, const float* __restrict__ h_init)
{
    int t = blockIdx.x * blockDim.x + threadIdx.x;
    if (t < 4 * 4 * HID) {
        int k = t >> 12; int rem = t & 4095; int g = rem >> 10; int hh = rem & 1023;
        const float* W = (g == 0) ? W_i : (g == 1) ? W_o : (g == 2) ? W_u : W_f;
        const float* b = (g == 0) ? b_i : (g == 1) ? b_o : (g == 2) ? b_u : b_f;
        const float* x = op_emb + k * KD;
        const float* w = W + (size_t)hh * KD;
        float acc = b[hh];
        for (int kk = 0; kk < KD; kk++) acc += x[kk] * w[kk];
        g_opg[t] = acc;
    } else if (t < 4 * 4 * HID + 3 * HID) {
        int t2 = t - 4 * 4 * HID; int g = t2 >> 10; int hh = t2 & 1023;
        const float* U = (g == 0) ? U_i : (g == 1) ? U_o : U_u;
        const float* b = (g == 0) ? b_i : (g == 1) ? b_o : b_u;
        const float* u = U + (size_t)hh * KD;
        float acc = b[hh];
        for (int kk = 0; kk < KD; kk++) acc += (h_init[kk] + h_init[KD + kk]) * u[kk];
        g_lc3[t2] = acc;
    } else if (t < 4 * 4 * HID + 3 * HID + 2 * HID) {
        int t2 = t - (4 * 4 * HID + 3 * HID); int ci = t2 >> 10; int hh = t2 & 1023;
        const float* u = U_f + (size_t)hh * KD;
        float acc = b_f[hh];
        for (int kk = 0; kk < KD; kk++) acc += h_init[ci * KD + kk] * u[kk];
        g_lf[t2] = acc;
    }
}

// ---------------- generic SGEMM, K fixed at 1024, C[M][N] = A' @ B^T -----------------
// MODE 0: A row r = A[r]           (plain)
// MODE 1: A row r = A[ids[r]]      (gather, leaves)
// MODE 2: A row r = A[2r] + A[2r+1] (child pair-sum)
// B is [N][K] row-major (weights). N multiple of 128. M arbitrary (guarded).
template <int MODE>
__global__ __launch_bounds__(256)
void sgemm_k1024(const float* __restrict__ A, const float* __restrict__ B,
                 float* __restrict__ C, int M, int N, const int* __restrict__ ids)
{
    __shared__ float As[8][128];
    __shared__ float Bs[8][128];
    const int tid  = threadIdx.x;
    const int tx   = tid & 15;        // 0..15 -> 8 cols each
    const int ty   = tid >> 4;        // 0..15 -> 8 rows each
    const int lrow = tid >> 1;        // 0..127
    const int lcol = (tid & 1) << 2;  // 0 or 4

    const int m0 = blockIdx.y * 128;
    const int n0 = blockIdx.x * 128;

    const bool arow_ok = (m0 + lrow) < M;
    const float* aptr0 = A;
    const float* aptr1 = A;
    if (arow_ok) {
        if (MODE == 0)      aptr0 = A + (size_t)(m0 + lrow) * KD;
        else if (MODE == 1) aptr0 = A + (size_t)ids[m0 + lrow] * KD;
        else { aptr0 = A + (size_t)(2 * (m0 + lrow)) * KD; aptr1 = aptr0 + KD; }
    }
    const float* bptr = B + (size_t)(n0 + lrow) * KD;

    float acc[8][8];
    #pragma unroll
    for (int i = 0; i < 8; i++)
        #pragma unroll
        for (int j = 0; j < 8; j++) acc[i][j] = 0.0f;

    for (int k0 = 0; k0 < KD; k0 += 8) {
        float4 av = make_float4(0.f, 0.f, 0.f, 0.f);
        if (arow_ok) {
            av = *(const float4*)(aptr0 + k0 + lcol);
            if (MODE == 2) {
                float4 a2 = *(const float4*)(aptr1 + k0 + lcol);
                av.x += a2.x; av.y += a2.y; av.z += a2.z; av.w += a2.w;
            }
        }
        float4 bv = *(const float4*)(bptr + k0 + lcol);
        As[lcol + 0][lrow] = av.x; As[lcol + 1][lrow] = av.y;
        As[lcol + 2][lrow] = av.z; As[lcol + 3][lrow] = av.w;
        Bs[lcol + 0][lrow] = bv.x; Bs[lcol + 1][lrow] = bv.y;
        Bs[lcol + 2][lrow] = bv.z; Bs[lcol + 3][lrow] = bv.w;
        __syncthreads();
        #pragma unroll
        for (int kk = 0; kk < 8; kk++) {
            float a[8], b[8];
            *(float4*)&a[0] = *(const float4*)&As[kk][ty * 8];
            *(float4*)&a[4] = *(const float4*)&As[kk][ty * 8 + 4];
            *(float4*)&b[0] = *(const float4*)&Bs[kk][tx * 8];
            *(float4*)&b[4] = *(const float4*)&Bs[kk][tx * 8 + 4];
            #pragma unroll
            for (int i = 0; i < 8; i++)
                #pragma unroll
                for (int j = 0; j < 8; j++) acc[i][j] += a[i] * b[j];
        }
        __syncthreads();
    }

    #pragma unroll
    for (int i = 0; i < 8; i++) {
        int row = m0 + ty * 8 + i;
        if (row < M) {
            float* crow = C + (size_t)row * N + n0 + tx * 8;
            *(float4*)(crow)     = make_float4(acc[i][0], acc[i][1], acc[i][2], acc[i][3]);
            *(float4*)(crow + 4) = make_float4(acc[i][4], acc[i][5], acc[i][6], acc[i][7]);
        }
    }
}

// ---------------- leaf gate epilogue -------------------------------------------------
__global__ void leaf_gate_kernel(const float* __restrict__ c_init,
                                 float* __restrict__ c_out, float* __restrict__ h_out)
{
    int idx = blockIdx.x * blockDim.x + threadIdx.x;  // < NLEAF*HID
    int hh = idx & 1023;
    int j = idx >> 10;
    const float* xw = g_xw + (size_t)j * 4 * HID;
    float i = sigf(xw[hh]          + g_lc3[hh]);
    float o = sigf(xw[HID + hh]    + g_lc3[HID + hh]);
    float u = tanhf(xw[2 * HID + hh] + g_lc3[2 * HID + hh]);
    float xf = xw[3 * HID + hh];
    float f0 = sigf(xf + g_lf[hh]);
    float f1 = sigf(xf + g_lf[HID + hh]);
    float c = i * u + f0 * c_init[hh] + f1 * c_init[HID + hh];
    c_out[idx] = c;
    h_out[idx] = o * tanhf(c);
}

// ---------------- internal node gate epilogue ----------------------------------------
__global__ void node_gate_kernel(int m, int off, const int* __restrict__ op_ids,
                                 const float* __restrict__ c_in,
                                 float* __restrict__ c_out, float* __restrict__ h_out)
{
    int idx = blockIdx.x * blockDim.x + threadIdx.x;
    if (idx >= m * HID) return;
    int hh = idx & 1023;
    int j = idx >> 10;
    const float* og = g_opg + op_ids[off + j] * 4 * HID;
    const float* g3 = g_g3 + (size_t)j * 3 * HID;
    float i = sigf(og[hh]            + g3[hh]);
    float o = sigf(og[HID + hh]      + g3[HID + hh]);
    float u = tanhf(og[2 * HID + hh] + g3[2 * HID + hh]);
    float xf = og[3 * HID + hh];
    float f0 = sigf(xf + g_gf[(size_t)(2 * j) * HID + hh]);
    float f1 = sigf(xf + g_gf[(size_t)(2 * j + 1) * HID + hh]);
    float c = i * u + f0 * c_in[(size_t)(2 * j) * HID + hh]
                    + f1 * c_in[(size_t)(2 * j + 1) * HID + hh];
    c_out[idx] = c;
    h_out[idx] = o * tanhf(c);
}

// ---------------- host launch --------------------------------------------------------
extern "C" void kernel_launch(void* const* d_in, const int* in_sizes, int n_in,
                              void* d_out, int out_size)
{
    const float* tokens   = (const float*)d_in[0];
    const int*   leaf_ids = (const int*)  d_in[1];
    const int*   op_ids   = (const int*)  d_in[2];
    const float* W_i = (const float*)d_in[3];
    const float* W_o = (const float*)d_in[4];
    const float* W_u = (const float*)d_in[5];
    const float* W_f = (const float*)d_in[6];
    const float* U_i = (const float*)d_in[7];
    const float* U_o = (const float*)d_in[8];
    const float* U_u = (const float*)d_in[9];
    const float* U_f = (const float*)d_in[10];
    const float* b_i = (const float*)d_in[11];
    const float* b_o = (const float*)d_in[12];
    const float* b_u = (const float*)d_in[13];
    const float* b_f = (const float*)d_in[14];
    const float* op_emb = (const float*)d_in[15];
    const float* c_init = (const float*)d_in[16];
    const float* h_init = (const float*)d_in[17];
    float* out = (float*)d_out;

    void* p;
    cudaGetSymbolAddress(&p, g_h);     float* hbase = (float*)p;
    cudaGetSymbolAddress(&p, g_c);     float* cbase = (float*)p;
    cudaGetSymbolAddress(&p, g_xw);    float* xw    = (float*)p;
    cudaGetSymbolAddress(&p, g_g3);    float* g3p   = (float*)p;
    cudaGetSymbolAddress(&p, g_gf);    float* gfp   = (float*)p;
    cudaGetSymbolAddress(&p, g_wcat);  float* wcat  = (float*)p;
    cudaGetSymbolAddress(&p, g_ucat3); float* ucat3 = (float*)p;

    float* hbuf[2] = { hbase, hbase + (size_t)NLEAF * HID };
    float* cbuf[2] = { cbase, cbase + (size_t)NLEAF * HID };

    const size_t WB = (size_t)HID * KD * sizeof(float);
    cudaMemcpyAsync(wcat + 0 * (size_t)HID * KD, W_i, WB, cudaMemcpyDeviceToDevice, 0);
    cudaMemcpyAsync(wcat + 1 * (size_t)HID * KD, W_o, WB, cudaMemcpyDeviceToDevice, 0);
    cudaMemcpyAsync(wcat + 2 * (size_t)HID * KD, W_u, WB, cudaMemcpyDeviceToDevice, 0);
    cudaMemcpyAsync(wcat + 3 * (size_t)HID * KD, W_f, WB, cudaMemcpyDeviceToDevice, 0);
    cudaMemcpyAsync(ucat3 + 0 * (size_t)HID * KD, U_i, WB, cudaMemcpyDeviceToDevice, 0);
    cudaMemcpyAsync(ucat3 + 1 * (size_t)HID * KD, U_o, WB, cudaMemcpyDeviceToDevice, 0);
    cudaMemcpyAsync(ucat3 + 2 * (size_t)HID * KD, U_u, WB, cudaMemcpyDeviceToDevice, 0);

    precompute_kernel<<<84, 256>>>(W_i, W_o, W_u, W_f, U_i, U_o, U_u, U_f,
                                   b_i, b_o, b_u, b_f, op_emb, h_init);

    // Leaf level: XW = tokens[leaf_ids] @ Wcat^T  (M=8192, N=4096)
    sgemm_k1024<1><<<dim3(4 * HID / 128, NLEAF / 128), 256>>>(
        tokens, wcat, xw, NLEAF, 4 * HID, leaf_ids);
    leaf_gate_kernel<<<NLEAF * HID / 256, 256>>>(c_init, cbuf[0], hbuf[0]);

    int cur = 0;
    for (int l = DEPTH - 1; l >= 0; l--) {
        int m = 1 << l;
        int off = m - 1;
        int nxt = cur ^ 1;
        // G3[m][3072] = (h[2j]+h[2j+1]) @ [Ui;Uo;Uu]^T   (pair-sum fused into loader)
        sgemm_k1024<2><<<dim3(3 * HID / 128, (m + 127) / 128), 256>>>(
            hbuf[cur], ucat3, g3p, m, 3 * HID, nullptr);
        // Gf[2m][1024] = h_child @ Uf^T
        sgemm_k1024<0><<<dim3(HID / 128, (2 * m + 127) / 128), 256>>>(
            hbuf[cur], U_f, gfp, 2 * m, HID, nullptr);
        node_gate_kernel<<<(m * HID + 255) / 256, 256>>>(
            m, off, op_ids, cbuf[cur], cbuf[nxt], hbuf[nxt]);
        cur = nxt;
    }

    // out = [c_root; h_root]  (2 x 1 x 1024)
    cudaMemcpyAsync(out,        cbuf[cur], HID * sizeof(float), cudaMemcpyDeviceToDevice, 0);
    cudaMemcpyAsync(out + HID,  hbuf[cur], HID * sizeof(float), cudaMemcpyDeviceToDevice, 0);
}

// round 5
// speedup vs baseline: 2.3871x; 2.3871x over previous
#include <cuda_runtime.h>
#include <cstdint>
#include <math.h>

#define HID 1024
#define KD  1024
#define NLEAF 8192
#define DEPTH 13

// ======================= device scratch =============================================
__device__ float g_h[2][NLEAF * HID];
__device__ float g_c[2][NLEAF * HID];
__device__ float g_xw[(size_t)NLEAF * 4 * HID];
__device__ float g_g3[(NLEAF / 2) * 3 * HID];
__device__ float g_gf[NLEAF * HID];
__device__ float g_wcat[4 * HID * KD];
__device__ float g_ucat3[3 * HID * KD];
__device__ float g_opg[4 * 4 * HID];
__device__ float g_lc3[3 * HID];
__device__ float g_lf[2 * HID];

__device__ __forceinline__ float sigf(float x) { return 1.0f / (1.0f + expf(-x)); }

__device__ __forceinline__ uint32_t f2tf(float x) {
    uint32_t r;
    asm("cvt.rna.tf32.f32 %0, %1;" : "=r"(r) : "f"(x));
    return r;
}

// ======================= precompute (exact fp32) ====================================
__global__ void precompute_kernel(
    const float* __restrict__ W_i, const float* __restrict__ W_o,
    const float* __restrict__ W_u, const float* __restrict__ W_f,
    const float* __restrict__ U_i, const float* __restrict__ U_o,
    const float* __restrict__ U_u, const float* __restrict__ U_f,
    const float* __restrict__ b_i, const float* __restrict__ b_o,
    const float* __restrict__ b_u, const float* __restrict__ b_f,
    const float* __restrict__ op_emb, const float* __restrict__ h_init)
{
    int t = blockIdx.x * blockDim.x + threadIdx.x;
    if (t < 4 * 4 * HID) {
        int k = t >> 12; int rem = t & 4095; int g = rem >> 10; int hh = rem & 1023;
        const float* W = (g == 0) ? W_i : (g == 1) ? W_o : (g == 2) ? W_u : W_f;
        const float* b = (g == 0) ? b_i : (g == 1) ? b_o : (g == 2) ? b_u : b_f;
        const float* x = op_emb + k * KD;
        const float* w = W + (size_t)hh * KD;
        float acc = b[hh];
        for (int kk = 0; kk < KD; kk++) acc += x[kk] * w[kk];
        g_opg[t] = acc;
    } else if (t < 4 * 4 * HID + 3 * HID) {
        int t2 = t - 4 * 4 * HID; int g = t2 >> 10; int hh = t2 & 1023;
        const float* U = (g == 0) ? U_i : (g == 1) ? U_o : U_u;
        const float* b = (g == 0) ? b_i : (g == 1) ? b_o : b_u;
        const float* u = U + (size_t)hh * KD;
        float acc = b[hh];
        for (int kk = 0; kk < KD; kk++) acc += (h_init[kk] + h_init[KD + kk]) * u[kk];
        g_lc3[t2] = acc;
    } else if (t < 4 * 4 * HID + 3 * HID + 2 * HID) {
        int t2 = t - (4 * 4 * HID + 3 * HID); int ci = t2 >> 10; int hh = t2 & 1023;
        const float* u = U_f + (size_t)hh * KD;
        float acc = b_f[hh];
        for (int kk = 0; kk < KD; kk++) acc += h_init[ci * KD + kk] * u[kk];
        g_lf[t2] = acc;
    }
}

// ======================= tf32 mma.sync GEMM, C[M][N] = A' @ B^T =====================
// MODE 0: A row r = A[r]; MODE 1: A row r = A[ids[r]]; MODE 2: A row r = A[2r]+A[2r+1]
// B is [N][KD] row-major. N multiple of 128. KD = 1024.
// CTA tile 128x128, K-chunk 32. 8 warps, each 32(M)x64(N) warptile of m16n8k8 frags.
// SMEM rows padded to 36 words -> fragment LDS bank = 4*gid + tig (conflict-free).
static constexpr int SMEM_STRIDE = 36;                 // 32 + 4 pad
static constexpr int BUF_WORDS   = 128 * SMEM_STRIDE;  // 4608 words per tile
static constexpr int GEMM_SMEM_BYTES = 2 * 2 * BUF_WORDS * 4;  // 73728

__device__ __forceinline__ void mma_tf32(float* c, const uint32_t* a, const uint32_t* b) {
    asm volatile(
        "mma.sync.aligned.m16n8k8.row.col.f32.tf32.tf32.f32 "
        "{%0,%1,%2,%3}, {%4,%5,%6,%7}, {%8,%9}, {%0,%1,%2,%3};"
        : "+f"(c[0]), "+f"(c[1]), "+f"(c[2]), "+f"(c[3])
        : "r"(a[0]), "r"(a[1]), "r"(a[2]), "r"(a[3]), "r"(b[0]), "r"(b[1]));
}

template <int MODE>
__global__ void __launch_bounds__(256, 1)
mma_gemm(const float* __restrict__ A, const float* __restrict__ B,
         float* __restrict__ C, int M, int N, const int* __restrict__ ids)
{
    extern __shared__ __align__(16) uint32_t sm[];
    // layout: [As0 | Bs0 | As1 | Bs1], each BUF_WORDS
    const int tid  = threadIdx.x;
    const int wid  = tid >> 5;
    const int lane = tid & 31;

    const int m0 = blockIdx.y * 128;
    const int n0 = blockIdx.x * 128;

    // ---- global loader mapping: 2 threads/row, 16 floats each (4 x float4) ----
    const int lrow = tid >> 1;
    const int fcol = (tid & 1) * 16;
    const bool aok = (m0 + lrow) < M;
    const float* aptr0 = A;
    const float* aptr1 = A;
    if (aok) {
        if (MODE == 0)      aptr0 = A + (size_t)(m0 + lrow) * KD;
        else if (MODE == 1) aptr0 = A + (size_t)ids[m0 + lrow] * KD;
        else { aptr0 = A + (size_t)(2 * (m0 + lrow)) * KD; aptr1 = aptr0 + KD; }
    }
    const float* bptr = B + (size_t)(n0 + lrow) * KD;

    // ---- warp tiling: 4 warps along M (32 each), 2 along N (64 each) ----
    const int wm  = (wid & 3) * 32;
    const int wn  = (wid >> 2) * 64;
    const int gid = lane >> 2;    // 0..7
    const int tig = lane & 3;     // 0..3

    float acc[2][8][4];
    #pragma unroll
    for (int mi = 0; mi < 2; mi++)
        #pragma unroll
        for (int ni = 0; ni < 8; ni++)
            #pragma unroll
            for (int e = 0; e < 4; e++) acc[mi][ni][e] = 0.0f;

    float4 av[4], bv[4];

    auto load_chunk = [&](int it) {
        const int k0 = it * 32;
        #pragma unroll
        for (int j = 0; j < 4; j++) {
            if (aok) {
                av[j] = *(const float4*)(aptr0 + k0 + fcol + j * 4);
                if (MODE == 2) {
                    float4 a2 = *(const float4*)(aptr1 + k0 + fcol + j * 4);
                    av[j].x += a2.x; av[j].y += a2.y; av[j].z += a2.z; av[j].w += a2.w;
                }
            } else {
                av[j] = make_float4(0.f, 0.f, 0.f, 0.f);
            }
            bv[j] = *(const float4*)(bptr + k0 + fcol + j * 4);
        }
    };
    auto store_chunk = [&](int b) {
        uint32_t* as = sm + b * 2 * BUF_WORDS;
        uint32_t* bs = as + BUF_WORDS;
        const int base = lrow * SMEM_STRIDE + fcol;
        #pragma unroll
        for (int j = 0; j < 4; j++) {
            uint4 ta = make_uint4(f2tf(av[j].x), f2tf(av[j].y), f2tf(av[j].z), f2tf(av[j].w));
            uint4 tb = make_uint4(f2tf(bv[j].x), f2tf(bv[j].y), f2tf(bv[j].z), f2tf(bv[j].w));
            *(uint4*)(as + base + j * 4) = ta;
            *(uint4*)(bs + base + j * 4) = tb;
        }
    };
    auto compute_chunk = [&](int b) {
        const uint32_t* as = sm + b * 2 * BUF_WORDS;
        const uint32_t* bs = as + BUF_WORDS;
        #pragma unroll
        for (int kk = 0; kk < 32; kk += 8) {
            uint32_t af[2][4], bf[8][2];
            #pragma unroll
            for (int mi = 0; mi < 2; mi++) {
                const int ab = (wm + mi * 16 + gid) * SMEM_STRIDE + kk + tig;
                af[mi][0] = as[ab];
                af[mi][1] = as[ab + 8 * SMEM_STRIDE];
                af[mi][2] = as[ab + 4];
                af[mi][3] = as[ab + 8 * SMEM_STRIDE + 4];
            }
            #pragma unroll
            for (int ni = 0; ni < 8; ni++) {
                const int bb = (wn + ni * 8 + gid) * SMEM_STRIDE + kk + tig;
                bf[ni][0] = bs[bb];
                bf[ni][1] = bs[bb + 4];
            }
            #pragma unroll
            for (int mi = 0; mi < 2; mi++)
                #pragma unroll
                for (int ni = 0; ni < 8; ni++)
                    mma_tf32(acc[mi][ni], af[mi], bf[ni]);
        }
    };

    load_chunk(0);
    store_chunk(0);
    __syncthreads();
    #pragma unroll 1
    for (int it = 0; it < 32; it++) {
        const int b = it & 1;
        if (it + 1 < 32) load_chunk(it + 1);   // LDGs in flight during mma
        compute_chunk(b);
        if (it + 1 < 32) {
            __syncthreads();                   // prior readers of buf b^1 done
            store_chunk(b ^ 1);
            __syncthreads();                   // buf b^1 ready
        }
    }

    // ---- epilogue ----
    #pragma unroll
    for (int mi = 0; mi < 2; mi++) {
        const int r0 = m0 + wm + mi * 16 + gid;
        const int r1 = r0 + 8;
        #pragma unroll
        for (int ni = 0; ni < 8; ni++) {
            const int col = n0 + wn + ni * 8 + tig * 2;
            if (r0 < M)
                *(float2*)(C + (size_t)r0 * N + col) = make_float2(acc[mi][ni][0], acc[mi][ni][1]);
            if (r1 < M)
                *(float2*)(C + (size_t)r1 * N + col) = make_float2(acc[mi][ni][2], acc[mi][ni][3]);
        }
    }
}

// ======================= gate epilogues =============================================
__global__ void leaf_gate_kernel(const float* __restrict__ c_init,
                                 float* __restrict__ c_out, float* __restrict__ h_out)
{
    int idx = blockIdx.x * blockDim.x + threadIdx.x;
    int hh = idx & 1023;
    int j = idx >> 10;
    const float* xw = g_xw + (size_t)j * 4 * HID;
    float i = sigf(xw[hh]            + g_lc3[hh]);
    float o = sigf(xw[HID + hh]      + g_lc3[HID + hh]);
    float u = tanhf(xw[2 * HID + hh] + g_lc3[2 * HID + hh]);
    float xf = xw[3 * HID + hh];
    float f0 = sigf(xf + g_lf[hh]);
    float f1 = sigf(xf + g_lf[HID + hh]);
    float c = i * u + f0 * c_init[hh] + f1 * c_init[HID + hh];
    c_out[idx] = c;
    h_out[idx] = o * tanhf(c);
}

__global__ void node_gate_kernel(int m, int off, const int* __restrict__ op_ids,
                                 const float* __restrict__ c_in,
                                 float* __restrict__ c_out, float* __restrict__ h_out)
{
    int idx = blockIdx.x * blockDim.x + threadIdx.x;
    if (idx >= m * HID) return;
    int hh = idx & 1023;
    int j = idx >> 10;
    const float* og = g_opg + op_ids[off + j] * 4 * HID;
    const float* g3 = g_g3 + (size_t)j * 3 * HID;
    float i = sigf(og[hh]            + g3[hh]);
    float o = sigf(og[HID + hh]      + g3[HID + hh]);
    float u = tanhf(og[2 * HID + hh] + g3[2 * HID + hh]);
    float xf = og[3 * HID + hh];
    float f0 = sigf(xf + g_gf[(size_t)(2 * j) * HID + hh]);
    float f1 = sigf(xf + g_gf[(size_t)(2 * j + 1) * HID + hh]);
    float c = i * u + f0 * c_in[(size_t)(2 * j) * HID + hh]
                    + f1 * c_in[(size_t)(2 * j + 1) * HID + hh];
    c_out[idx] = c;
    h_out[idx] = o * tanhf(c);
}

// ======================= host launch ================================================
extern "C" void kernel_launch(void* const* d_in, const int* in_sizes, int n_in,
                              void* d_out, int out_size)
{
    const float* tokens   = (const float*)d_in[0];
    const int*   leaf_ids = (const int*)  d_in[1];
    const int*   op_ids   = (const int*)  d_in[2];
    const float* W_i = (const float*)d_in[3];
    const float* W_o = (const float*)d_in[4];
    const float* W_u = (const float*)d_in[5];
    const float* W_f = (const float*)d_in[6];
    const float* U_i = (const float*)d_in[7];
    const float* U_o = (const float*)d_in[8];
    const float* U_u = (const float*)d_in[9];
    const float* U_f = (const float*)d_in[10];
    const float* b_i = (const float*)d_in[11];
    const float* b_o = (const float*)d_in[12];
    const float* b_u = (const float*)d_in[13];
    const float* b_f = (const float*)d_in[14];
    const float* op_emb = (const float*)d_in[15];
    const float* c_init = (const float*)d_in[16];
    const float* h_init = (const float*)d_in[17];
    float* out = (float*)d_out;

    cudaFuncSetAttribute(mma_gemm<0>, cudaFuncAttributeMaxDynamicSharedMemorySize, GEMM_SMEM_BYTES);
    cudaFuncSetAttribute(mma_gemm<1>, cudaFuncAttributeMaxDynamicSharedMemorySize, GEMM_SMEM_BYTES);
    cudaFuncSetAttribute(mma_gemm<2>, cudaFuncAttributeMaxDynamicSharedMemorySize, GEMM_SMEM_BYTES);

    void* p;
    cudaGetSymbolAddress(&p, g_h);     float* hbase = (float*)p;
    cudaGetSymbolAddress(&p, g_c);     float* cbase = (float*)p;
    cudaGetSymbolAddress(&p, g_xw);    float* xw    = (float*)p;
    cudaGetSymbolAddress(&p, g_g3);    float* g3p   = (float*)p;
    cudaGetSymbolAddress(&p, g_gf);    float* gfp   = (float*)p;
    cudaGetSymbolAddress(&p, g_wcat);  float* wcat  = (float*)p;
    cudaGetSymbolAddress(&p, g_ucat3); float* ucat3 = (float*)p;

    float* hbuf[2] = { hbase, hbase + (size_t)NLEAF * HID };
    float* cbuf[2] = { cbase, cbase + (size_t)NLEAF * HID };

    const size_t WB = (size_t)HID * KD * sizeof(float);
    cudaMemcpyAsync(wcat + 0 * (size_t)HID * KD, W_i, WB, cudaMemcpyDeviceToDevice, 0);
    cudaMemcpyAsync(wcat + 1 * (size_t)HID * KD, W_o, WB, cudaMemcpyDeviceToDevice, 0);
    cudaMemcpyAsync(wcat + 2 * (size_t)HID * KD, W_u, WB, cudaMemcpyDeviceToDevice, 0);
    cudaMemcpyAsync(wcat + 3 * (size_t)HID * KD, W_f, WB, cudaMemcpyDeviceToDevice, 0);
    cudaMemcpyAsync(ucat3 + 0 * (size_t)HID * KD, U_i, WB, cudaMemcpyDeviceToDevice, 0);
    cudaMemcpyAsync(ucat3 + 1 * (size_t)HID * KD, U_o, WB, cudaMemcpyDeviceToDevice, 0);
    cudaMemcpyAsync(ucat3 + 2 * (size_t)HID * KD, U_u, WB, cudaMemcpyDeviceToDevice, 0);

    precompute_kernel<<<84, 256>>>(W_i, W_o, W_u, W_f, U_i, U_o, U_u, U_f,
                                   b_i, b_o, b_u, b_f, op_emb, h_init);

    // Leaf level: XW = tokens[leaf_ids] @ Wcat^T  (M=8192, N=4096)
    mma_gemm<1><<<dim3(4 * HID / 128, NLEAF / 128), 256, GEMM_SMEM_BYTES>>>(
        tokens, wcat, xw, NLEAF, 4 * HID, leaf_ids);
    leaf_gate_kernel<<<NLEAF * HID / 256, 256>>>(c_init, cbuf[0], hbuf[0]);

    int cur = 0;
    for (int l = DEPTH - 1; l >= 0; l--) {
        int m = 1 << l;
        int off = m - 1;
        int nxt = cur ^ 1;
        // G3[m][3072] = (h[2j]+h[2j+1]) @ [Ui;Uo;Uu]^T
        mma_gemm<2><<<dim3(3 * HID / 128, (m + 127) / 128), 256, GEMM_SMEM_BYTES>>>(
            hbuf[cur], ucat3, g3p, m, 3 * HID, nullptr);
        // Gf[2m][1024] = h_child @ Uf^T
        mma_gemm<0><<<dim3(HID / 128, (2 * m + 127) / 128), 256, GEMM_SMEM_BYTES>>>(
            hbuf[cur], U_f, gfp, 2 * m, HID, nullptr);
        node_gate_kernel<<<(m * HID + 255) / 256, 256>>>(
            m, off, op_ids, cbuf[cur], cbuf[nxt], hbuf[nxt]);
        cur = nxt;
    }

    cudaMemcpyAsync(out,       cbuf[cur], HID * sizeof(float), cudaMemcpyDeviceToDevice, 0);
    cudaMemcpyAsync(out + HID, hbuf[cur], HID * sizeof(float), cudaMemcpyDeviceToDevice, 0);
}

// round 7
// speedup vs baseline: 2.5701x; 1.0767x over previous
#include <cuda_runtime.h>
#include <cstdint>
#include <math.h>

#define HID 1024
#define KD  1024
#define NLEAF 8192
#define DEPTH 13

// ======================= device scratch =============================================
__device__ float g_h[2][NLEAF * HID];
__device__ float g_c[2][NLEAF * HID];
__device__ float g_hs[(NLEAF / 2) * HID];      // pair-summed child h
__device__ float g_xw[(size_t)NLEAF * 4 * HID];
__device__ float g_g3[(NLEAF / 2) * 3 * HID];
__device__ float g_gf[NLEAF * HID];
__device__ float g_wcat[4 * HID * KD];
__device__ float g_ucat3[3 * HID * KD];
__device__ float g_opg[4 * 4 * HID];
__device__ float g_lc3[3 * HID];
__device__ float g_lf[2 * HID];

__device__ __forceinline__ float sigf(float x) { return 1.0f / (1.0f + expf(-x)); }

__device__ __forceinline__ uint32_t f2tf(float x) {
    uint32_t r;
    asm("cvt.rna.tf32.f32 %0, %1;" : "=r"(r) : "f"(x));
    return r;
}
__device__ __forceinline__ uint32_t smem_u32(const void* p) {
    uint32_t a;
    asm("{ .reg .u64 t; cvta.to.shared.u64 t, %1; cvt.u32.u64 %0, t; }" : "=r"(a) : "l"(p));
    return a;
}
__device__ __forceinline__ void cp_async16(uint32_t dst, const void* src, int src_bytes) {
    asm volatile("cp.async.cg.shared.global [%0], [%1], 16, %2;"
                 :: "r"(dst), "l"(src), "r"(src_bytes) : "memory");
}

// ======================= precompute (exact fp32) ====================================
__global__ void precompute_kernel(
    const float* __restrict__ W_i, const float* __restrict__ W_o,
    const float* __restrict__ W_u, const float* __restrict__ W_f,
    const float* __restrict__ U_i, const float* __restrict__ U_o,
    const float* __restrict__ U_u, const float* __restrict__ U_f,
    const float* __restrict__ b_i, const float* __restrict__ b_o,
    const float* __restrict__ b_u, const float* __restrict__ b_f,
    const float* __restrict__ op_emb, const float* __restrict__ h_init)
{
    int t = blockIdx.x * blockDim.x + threadIdx.x;
    if (t < 4 * 4 * HID) {
        int k = t >> 12; int rem = t & 4095; int g = rem >> 10; int hh = rem & 1023;
        const float* W = (g == 0) ? W_i : (g == 1) ? W_o : (g == 2) ? W_u : W_f;
        const float* b = (g == 0) ? b_i : (g == 1) ? b_o : (g == 2) ? b_u : b_f;
        const float* x = op_emb + k * KD;
        const float* w = W + (size_t)hh * KD;
        float acc = b[hh];
        for (int kk = 0; kk < KD; kk++) acc += x[kk] * w[kk];
        g_opg[t] = acc;
    } else if (t < 4 * 4 * HID + 3 * HID) {
        int t2 = t - 4 * 4 * HID; int g = t2 >> 10; int hh = t2 & 1023;
        const float* U = (g == 0) ? U_i : (g == 1) ? U_o : U_u;
        const float* b = (g == 0) ? b_i : (g == 1) ? b_o : b_u;
        const float* u = U + (size_t)hh * KD;
        float acc = b[hh];
        for (int kk = 0; kk < KD; kk++) acc += (h_init[kk] + h_init[KD + kk]) * u[kk];
        g_lc3[t2] = acc;
    } else if (t < 4 * 4 * HID + 3 * HID + 2 * HID) {
        int t2 = t - (4 * 4 * HID + 3 * HID); int ci = t2 >> 10; int hh = t2 & 1023;
        const float* u = U_f + (size_t)hh * KD;
        float acc = b_f[hh];
        for (int kk = 0; kk < KD; kk++) acc += h_init[ci * KD + kk] * u[kk];
        g_lf[t2] = acc;
    }
}

// ======================= tf32 mma.sync GEMM, C[M][N] = A' @ B^T =====================
// GATHER=0: A row r = A[r];  GATHER=1: A row r = A[ids[r]].
// B is [N][KD] row-major. N multiple of 128. KD = 1024.
// CTA 128x128 tile, K-chunk 32, 3-stage cp.async pipeline, 512 threads.
// 16 warps, each a 32x32 warptile of m16n8k8 tf32 frags; fp32 in smem, cvt at use.
// SMEM rows padded to 36 words -> fragment lds bank = 4*gid + tig (conflict-free).
static constexpr int SMEM_STRIDE = 36;
static constexpr int STAGE_WORDS = 256 * SMEM_STRIDE;              // A(128)+B(128) rows
static constexpr int NSTAGE = 3;
static constexpr int GEMM_SMEM_BYTES = NSTAGE * STAGE_WORDS * 4;   // 110592

__device__ __forceinline__ void mma_tf32(float* c, const uint32_t* a, const uint32_t* b) {
    asm volatile(
        "mma.sync.aligned.m16n8k8.row.col.f32.tf32.tf32.f32 "
        "{%0,%1,%2,%3}, {%4,%5,%6,%7}, {%8,%9}, {%0,%1,%2,%3};"
        : "+f"(c[0]), "+f"(c[1]), "+f"(c[2]), "+f"(c[3])
        : "r"(a[0]), "r"(a[1]), "r"(a[2]), "r"(a[3]), "r"(b[0]), "r"(b[1]));
}

template <int GATHER>
__global__ void __launch_bounds__(512, 1)
mma_gemm(const float* __restrict__ A, const float* __restrict__ B,
         float* __restrict__ C, int M, int N, const int* __restrict__ ids)
{
    extern __shared__ __align__(16) uint32_t sm[];
    const int tid  = threadIdx.x;
    const int wid  = tid >> 5;
    const int lane = tid & 31;
    const int m0 = blockIdx.y * 128;
    const int n0 = blockIdx.x * 128;

    // ---- loader mapping: 2 threads per row (256 rows: 0-127 A, 128-255 B) ----
    const int lrow = tid >> 1;
    const int fcol = (tid & 1) * 16;         // 16 floats = 4 x 16B per thread
    const float* src;
    int srcsz = 16;
    if (lrow < 128) {
        const int r = m0 + lrow;
        const bool ok = r < M;
        const int rr = ok ? (GATHER ? ids[r] : r) : 0;
        src = A + (size_t)rr * KD + fcol;
        srcsz = ok ? 16 : 0;
    } else {
        src = B + (size_t)(n0 + lrow - 128) * KD + fcol;
    }
    const uint32_t dbase = smem_u32(sm) + (uint32_t)(lrow * SMEM_STRIDE + fcol) * 4;

    auto issue = [&](int it) {
        const uint32_t d = dbase + (uint32_t)(it % NSTAGE) * (STAGE_WORDS * 4);
        const float* p = src + it * 32;
        #pragma unroll
        for (int j = 0; j < 4; j++)
            cp_async16(d + j * 16, p + j * 4, srcsz);
        asm volatile("cp.async.commit_group;" ::: "memory");
    };

    // ---- warp tiling: 4x4 grid of 32x32 warptiles ----
    const int wm  = (wid & 3) * 32;
    const int wn  = (wid >> 2) * 32;
    const int gid = lane >> 2;
    const int tig = lane & 3;

    float acc[2][4][4];
    #pragma unroll
    for (int mi = 0; mi < 2; mi++)
        #pragma unroll
        for (int ni = 0; ni < 4; ni++)
            #pragma unroll
            for (int e = 0; e < 4; e++) acc[mi][ni][e] = 0.0f;

    auto compute = [&](int s) {
        const uint32_t* st = sm + s * STAGE_WORDS;
        #pragma unroll
        for (int kk = 0; kk < 32; kk += 8) {
            uint32_t af[2][4], bf[4][2];
            #pragma unroll
            for (int mi = 0; mi < 2; mi++) {
                const uint32_t* ap = st + (wm + mi * 16 + gid) * SMEM_STRIDE + kk + tig;
                af[mi][0] = f2tf(__uint_as_float(ap[0]));
                af[mi][1] = f2tf(__uint_as_float(ap[8 * SMEM_STRIDE]));
                af[mi][2] = f2tf(__uint_as_float(ap[4]));
                af[mi][3] = f2tf(__uint_as_float(ap[8 * SMEM_STRIDE + 4]));
            }
            #pragma unroll
            for (int ni = 0; ni < 4; ni++) {
                const uint32_t* bp = st + (128 + wn + ni * 8 + gid) * SMEM_STRIDE + kk + tig;
                bf[ni][0] = f2tf(__uint_as_float(bp[0]));
                bf[ni][1] = f2tf(__uint_as_float(bp[4]));
            }
            #pragma unroll
            for (int mi = 0; mi < 2; mi++)
                #pragma unroll
                for (int ni = 0; ni < 4; ni++)
                    mma_tf32(acc[mi][ni], af[mi], bf[ni]);
        }
    };

    issue(0);
    issue(1);
    #pragma unroll 1
    for (int it = 0; it < 32; it++) {
        if (it < 30) { asm volatile("cp.async.wait_group 1;" ::: "memory"); }
        else         { asm volatile("cp.async.wait_group 0;" ::: "memory"); }
        __syncthreads();
        compute(it % NSTAGE);
        if (it + 2 < 32) issue(it + 2);
    }

    // ---- epilogue ----
    #pragma unroll
    for (int mi = 0; mi < 2; mi++) {
        const int r0 = m0 + wm + mi * 16 + gid;
        #pragma unroll
        for (int ni = 0; ni < 4; ni++) {
            const int col = n0 + wn + ni * 8 + tig * 2;
            if (r0 < M)
                *(float2*)(C + (size_t)r0 * N + col) = make_float2(acc[mi][ni][0], acc[mi][ni][1]);
            if (r0 + 8 < M)
                *(float2*)(C + (size_t)(r0 + 8) * N + col) = make_float2(acc[mi][ni][2], acc[mi][ni][3]);
        }
    }
}

// ======================= gate epilogues (pair-fused: also emit hs) ==================
__global__ void leaf_gate_pair_kernel(const float* __restrict__ c_init,
                                      float* __restrict__ c_out, float* __restrict__ h_out,
                                      float* __restrict__ hs_out)
{
    int idx = blockIdx.x * blockDim.x + threadIdx.x;   // < (NLEAF/2)*HID
    int hh = idx & 1023;
    int p = idx >> 10;
    const float ci0 = c_init[hh], ci1 = c_init[HID + hh];
    const float lci = g_lc3[hh], lco = g_lc3[HID + hh], lcu = g_lc3[2 * HID + hh];
    const float lf0 = g_lf[hh], lf1 = g_lf[HID + hh];
    float hsum = 0.0f;
    #pragma unroll
    for (int s = 0; s < 2; s++) {
        const int j = 2 * p + s;
        const float* xw = g_xw + (size_t)j * 4 * HID;
        float i = sigf(xw[hh] + lci);
        float o = sigf(xw[HID + hh] + lco);
        float u = tanhf(xw[2 * HID + hh] + lcu);
        float xf = xw[3 * HID + hh];
        float c = i * u + sigf(xf + lf0) * ci0 + sigf(xf + lf1) * ci1;
        float h = o * tanhf(c);
        c_out[(size_t)j * HID + hh] = c;
        h_out[(size_t)j * HID + hh] = h;
        hsum += h;
    }
    hs_out[(size_t)p * HID + hh] = hsum;
}

__global__ void node_gate_pair_kernel(int m, int off, const int* __restrict__ op_ids,
                                      const float* __restrict__ c_in,
                                      float* __restrict__ c_out, float* __restrict__ h_out,
                                      float* __restrict__ hs_out)
{
    int idx = blockIdx.x * blockDim.x + threadIdx.x;
    if (idx >= (m >> 1) * HID) return;
    int hh = idx & 1023;
    int p = idx >> 10;
    float hsum = 0.0f;
    #pragma unroll
    for (int s = 0; s < 2; s++) {
        const int j = 2 * p + s;
        const float* og = g_opg + op_ids[off + j] * 4 * HID;
        const float* g3 = g_g3 + (size_t)j * 3 * HID;
        float i = sigf(og[hh]            + g3[hh]);
        float o = sigf(og[HID + hh]      + g3[HID + hh]);
        float u = tanhf(og[2 * HID + hh] + g3[2 * HID + hh]);
        float xf = og[3 * HID + hh];
        float f0 = sigf(xf + g_gf[(size_t)(2 * j) * HID + hh]);
        float f1 = sigf(xf + g_gf[(size_t)(2 * j + 1) * HID + hh]);
        float c = i * u + f0 * c_in[(size_t)(2 * j) * HID + hh]
                        + f1 * c_in[(size_t)(2 * j + 1) * HID + hh];
        float h = o * tanhf(c);
        c_out[(size_t)j * HID + hh] = c;
        h_out[(size_t)j * HID + hh] = h;
        hsum += h;
    }
    hs_out[(size_t)p * HID + hh] = hsum;
}

__global__ void node_gate_root_kernel(const int* __restrict__ op_ids,
                                      const float* __restrict__ c_in,
                                      float* __restrict__ c_out, float* __restrict__ h_out)
{
    int hh = blockIdx.x * blockDim.x + threadIdx.x;
    if (hh >= HID) return;
    const float* og = g_opg + op_ids[0] * 4 * HID;
    float i = sigf(og[hh]            + g_g3[hh]);
    float o = sigf(og[HID + hh]      + g_g3[HID + hh]);
    float u = tanhf(og[2 * HID + hh] + g_g3[2 * HID + hh]);
    float xf = og[3 * HID + hh];
    float f0 = sigf(xf + g_gf[hh]);
    float f1 = sigf(xf + g_gf[HID + hh]);
    float c = i * u + f0 * c_in[hh] + f1 * c_in[HID + hh];
    c_out[hh] = c;
    h_out[hh] = o * tanhf(c);
}

// ======================= host launch ================================================
extern "C" void kernel_launch(void* const* d_in, const int* in_sizes, int n_in,
                              void* d_out, int out_size)
{
    const float* tokens   = (const float*)d_in[0];
    const int*   leaf_ids = (const int*)  d_in[1];
    const int*   op_ids   = (const int*)  d_in[2];
    const float* W_i = (const float*)d_in[3];
    const float* W_o = (const float*)d_in[4];
    const float* W_u = (const float*)d_in[5];
    const float* W_f = (const float*)d_in[6];
    const float* U_i = (const float*)d_in[7];
    const float* U_o = (const float*)d_in[8];
    const float* U_u = (const float*)d_in[9];
    const float* U_f = (const float*)d_in[10];
    const float* b_i = (const float*)d_in[11];
    const float* b_o = (const float*)d_in[12];
    const float* b_u = (const float*)d_in[13];
    const float* b_f = (const float*)d_in[14];
    const float* op_emb = (const float*)d_in[15];
    const float* c_init = (const float*)d_in[16];
    const float* h_init = (const float*)d_in[17];
    float* out = (float*)d_out;

    cudaFuncSetAttribute(mma_gemm<0>, cudaFuncAttributeMaxDynamicSharedMemorySize, GEMM_SMEM_BYTES);
    cudaFuncSetAttribute(mma_gemm<1>, cudaFuncAttributeMaxDynamicSharedMemorySize, GEMM_SMEM_BYTES);

    void* p;
    cudaGetSymbolAddress(&p, g_h);     float* hbase = (float*)p;
    cudaGetSymbolAddress(&p, g_c);     float* cbase = (float*)p;
    cudaGetSymbolAddress(&p, g_hs);    float* hsp   = (float*)p;
    cudaGetSymbolAddress(&p, g_xw);    float* xw    = (float*)p;
    cudaGetSymbolAddress(&p, g_g3);    float* g3p   = (float*)p;
    cudaGetSymbolAddress(&p, g_gf);    float* gfp   = (float*)p;
    cudaGetSymbolAddress(&p, g_wcat);  float* wcat  = (float*)p;
    cudaGetSymbolAddress(&p, g_ucat3); float* ucat3 = (float*)p;

    float* hbuf[2] = { hbase, hbase + (size_t)NLEAF * HID };
    float* cbuf[2] = { cbase, cbase + (size_t)NLEAF * HID };

    const size_t WB = (size_t)HID * KD * sizeof(float);
    cudaMemcpyAsync(wcat + 0 * (size_t)HID * KD, W_i, WB, cudaMemcpyDeviceToDevice, 0);
    cudaMemcpyAsync(wcat + 1 * (size_t)HID * KD, W_o, WB, cudaMemcpyDeviceToDevice, 0);
    cudaMemcpyAsync(wcat + 2 * (size_t)HID * KD, W_u, WB, cudaMemcpyDeviceToDevice, 0);
    cudaMemcpyAsync(wcat + 3 * (size_t)HID * KD, W_f, WB, cudaMemcpyDeviceToDevice, 0);
    cudaMemcpyAsync(ucat3 + 0 * (size_t)HID * KD, U_i, WB, cudaMemcpyDeviceToDevice, 0);
    cudaMemcpyAsync(ucat3 + 1 * (size_t)HID * KD, U_o, WB, cudaMemcpyDeviceToDevice, 0);
    cudaMemcpyAsync(ucat3 + 2 * (size_t)HID * KD, U_u, WB, cudaMemcpyDeviceToDevice, 0);

    precompute_kernel<<<84, 256>>>(W_i, W_o, W_u, W_f, U_i, U_o, U_u, U_f,
                                   b_i, b_o, b_u, b_f, op_emb, h_init);

    // Leaf level: XW = tokens[leaf_ids] @ Wcat^T  (M=8192, N=4096)
    mma_gemm<1><<<dim3(4 * HID / 128, NLEAF / 128), 512, GEMM_SMEM_BYTES>>>(
        tokens, wcat, xw, NLEAF, 4 * HID, leaf_ids);
    leaf_gate_pair_kernel<<<(NLEAF / 2) * HID / 256, 256>>>(c_init, cbuf[0], hbuf[0], hsp);

    int cur = 0;
    for (int l = DEPTH - 1; l >= 0; l--) {
        const int m = 1 << l;
        const int off = m - 1;
        const int nxt = cur ^ 1;
        // G3[m][3072] = hs @ [Ui;Uo;Uu]^T
        mma_gemm<0><<<dim3(3 * HID / 128, (m + 127) / 128), 512, GEMM_SMEM_BYTES>>>(
            hsp, ucat3, g3p, m, 3 * HID, nullptr);
        // Gf[2m][1024] = h_child @ Uf^T
        mma_gemm<0><<<dim3(HID / 128, (2 * m + 127) / 128), 512, GEMM_SMEM_BYTES>>>(
            hbuf[cur], U_f, gfp, 2 * m, HID, nullptr);
        if (m > 1) {
            node_gate_pair_kernel<<<((m / 2) * HID + 255) / 256, 256>>>(
                m, off, op_ids, cbuf[cur], cbuf[nxt], hbuf[nxt], hsp);
        } else {
            node_gate_root_kernel<<<4, 256>>>(op_ids, cbuf[cur], cbuf[nxt], hbuf[nxt]);
        }
        cur = nxt;
    }

    cudaMemcpyAsync(out,       cbuf[cur], HID * sizeof(float), cudaMemcpyDeviceToDevice, 0);
    cudaMemcpyAsync(out + HID, hbuf[cur], HID * sizeof(float), cudaMemcpyDeviceToDevice, 0);
}